// round 1
// baseline (speedup 1.0000x reference)
#include <cuda_runtime.h>
#include <cstdint>

// LinformerAttention: B=4, N=4096, D=1024, H=16, R=64, HD=64
//
// Restructured math (exactly equivalent to reference, fp32 throughout):
//   xE[b,r,d]  = sum_n E[n,r]  * x[b,n,d]
//   xF[b,r,d]  = sum_n Fm[n,r] * x[b,n,d]
//   KL[b,r,e]  = sum_d xE[b,r,d] * Wk[e,d]        (e = h*64+hd)
//   VL[b,r,e]  = sum_d xF[b,r,d] * Wv[e,d]
//   Wt[b,h*64+r,d] = (1/sqrt(64)) * sum_hd KL[b,r,h*64+hd] * Wq[h*64+hd,d]
//   Mt[b,e,h*64+r] =                sum_hd VL[b,r,h*64+hd] * Wo[e,h*64+hd]
//   S[b,n,j]   = sum_d x[b,n,d] * Wt[b,j,d]       (j = h*64+r)  -> softmax per 64-group
//   out[b,n,e] = sum_j S[b,n,j] * Mt[b,e,j] + bo[e]

#define B_ 4
#define N_ 4096
#define D_ 1024
#define H_ 16
#define R_ 64

#define OFF_XE 0
#define OFF_XF (OFF_XE + B_*R_*D_)
#define OFF_KL (OFF_XF + B_*R_*D_)
#define OFF_VL (OFF_KL + B_*R_*D_)
#define OFF_WT (OFF_VL + B_*R_*D_)
#define OFF_MT (OFF_WT + B_*D_*D_)
#define OFF_S  (OFF_MT + B_*D_*D_)
#define SCRATCH_TOTAL (OFF_S + B_*N_*D_)

__device__ float g_scratch[SCRATCH_TOTAL];  // ~100 MB static scratch (no allocs)

// ---------------------------------------------------------------------------
// Kernel 1: low-rank sequence reduction.  xE/xF[b,r,d] = sum_n P[n,r]*x[b,n,d]
// grid: (16 d-tiles, 4 b, 2 which), block 256 (16x16), 4x4 thread tile (64x64 out)
// ---------------------------------------------------------------------------
__global__ __launch_bounds__(256)
void lowrank_kernel(const float* __restrict__ x,
                    const float* __restrict__ E,
                    const float* __restrict__ Fm,
                    float* __restrict__ xE,
                    float* __restrict__ xF)
{
    __shared__ float Ps[32][64];
    __shared__ float Xs[32][64];
    const float* P = blockIdx.z ? Fm : E;
    float* OUT = blockIdx.z ? xF : xE;
    const int b = blockIdx.y;
    const int d0 = blockIdx.x * 64;
    const int t = threadIdx.x;
    const int tx = t & 15, ty = t >> 4;
    const float* xb = x + (long)b * N_ * D_;

    float acc[4][4];
#pragma unroll
    for (int i = 0; i < 4; i++)
#pragma unroll
        for (int j = 0; j < 4; j++) acc[i][j] = 0.f;

    for (int n0 = 0; n0 < N_; n0 += 32) {
#pragma unroll
        for (int l = t; l < 512; l += 256) {   // 32 rows x 16 float4s
            int row = l >> 4, q = (l & 15) * 4;
            *(float4*)&Ps[row][q] = *(const float4*)&P[(long)(n0 + row) * R_ + q];
            *(float4*)&Xs[row][q] = *(const float4*)&xb[(long)(n0 + row) * D_ + d0 + q];
        }
        __syncthreads();
#pragma unroll
        for (int n = 0; n < 32; n++) {
            float4 a = *(float4*)&Ps[n][ty * 4];
            float4 c = *(float4*)&Xs[n][tx * 4];
            float ra[4] = {a.x, a.y, a.z, a.w};
            float rc[4] = {c.x, c.y, c.z, c.w};
#pragma unroll
            for (int i = 0; i < 4; i++)
#pragma unroll
                for (int j = 0; j < 4; j++)
                    acc[i][j] += ra[i] * rc[j];
        }
        __syncthreads();
    }
#pragma unroll
    for (int i = 0; i < 4; i++) {
        float4 v = make_float4(acc[i][0], acc[i][1], acc[i][2], acc[i][3]);
        *(float4*)&OUT[((long)b * R_ + ty * 4 + i) * D_ + d0 + tx * 4] = v;
    }
}

// ---------------------------------------------------------------------------
// Generic tiled GEMM:  C = alpha * A (MxK, K-contig) * B^T (+bias per column)
//   b_is_kn == 0 : B stored [N][K], K contiguous (NT)
//   b_is_kn == 1 : B stored [K][N], N contiguous (NN)
// Batch offset for blockIdx.z:  off = (z/zdiv)*s1 + (z%zdiv)*s2  per operand.
// 256 threads; BM*BK == 1024, BN*BK == 1024 (one float4 per operand per tile).
// Double-buffered smem, padded transposed tiles for conflict-free access.
// ---------------------------------------------------------------------------
template<int BM, int BN, int TM, int TN, int BK>
__global__ __launch_bounds__(256)
void gemm_nt_kernel(const float* __restrict__ Ag, int lda,
                    const float* __restrict__ Bg, int ldb,
                    float* __restrict__ Cg, int ldc,
                    int M, int N, int K,
                    float alpha, const float* __restrict__ bias,
                    int zdiv,
                    long sA1, long sA2, long sB1, long sB2, long sC1, long sC2,
                    int b_is_kn)
{
    static_assert(BM * BK == 1024 && BN * BK == 1024, "load mapping");
    static_assert((BN / TN) * (BM / TM) == 256, "thread grid");
    constexpr int GPA = BM + 4;
    constexpr int GPB = BN + 4;
    __shared__ float As[2][BK * GPA];
    __shared__ float Bs[2][BK * GPB];

    const int z = blockIdx.z;
    const long z1 = z / zdiv, z2 = z % zdiv;
    const float* A = Ag + z1 * sA1 + z2 * sA2;
    const float* Bp = Bg + z1 * sB1 + z2 * sB2;
    float* C = Cg + z1 * sC1 + z2 * sC2;

    const int m0 = blockIdx.y * BM;
    const int n0 = blockIdx.x * BN;
    const int t  = threadIdx.x;
    const int tx = t % (BN / TN);
    const int ty = t / (BN / TN);

    constexpr int KQ = BK / 4;
    const int arow = t / KQ;            // 0..BM-1
    const int akq  = (t % KQ) * 4;      // k offset within tile
    const int bkrow = t / (BN / 4);     // NN path: 0..BK-1
    const int bnq   = (t % (BN / 4)) * 4;

    const bool amask = (m0 + arow) < M;
    const bool bmask_nt = (n0 + arow) < N;   // NT B uses same row mapping as A
    const bool bmask_nn = (n0 + bnq) < N;

    float acc[TM][TN];
#pragma unroll
    for (int i = 0; i < TM; i++)
#pragma unroll
        for (int j = 0; j < TN; j++) acc[i][j] = 0.f;

    float4 pa, pb;
    const float4 z4 = make_float4(0.f, 0.f, 0.f, 0.f);

    auto ldA = [&](int k0) {
        pa = amask ? *(const float4*)(A + (long)(m0 + arow) * lda + k0 + akq) : z4;
    };
    auto ldB = [&](int k0) {
        if (b_is_kn)
            pb = bmask_nn ? *(const float4*)(Bp + (long)(k0 + bkrow) * ldb + n0 + bnq) : z4;
        else
            pb = bmask_nt ? *(const float4*)(Bp + (long)(n0 + arow) * ldb + k0 + akq) : z4;
    };
    auto stA = [&](int buf) {
        As[buf][(akq + 0) * GPA + arow] = pa.x;
        As[buf][(akq + 1) * GPA + arow] = pa.y;
        As[buf][(akq + 2) * GPA + arow] = pa.z;
        As[buf][(akq + 3) * GPA + arow] = pa.w;
    };
    auto stB = [&](int buf) {
        if (b_is_kn) {
            *(float4*)&Bs[buf][bkrow * GPB + bnq] = pb;
        } else {
            Bs[buf][(akq + 0) * GPB + arow] = pb.x;
            Bs[buf][(akq + 1) * GPB + arow] = pb.y;
            Bs[buf][(akq + 2) * GPB + arow] = pb.z;
            Bs[buf][(akq + 3) * GPB + arow] = pb.w;
        }
    };

    ldA(0); ldB(0);
    stA(0); stB(0);
    __syncthreads();

    const int nk = K / BK;
    int buf = 0;
    for (int kt = 0; kt < nk; kt++) {
        if (kt + 1 < nk) { ldA((kt + 1) * BK); ldB((kt + 1) * BK); }
#pragma unroll
        for (int kk = 0; kk < BK; kk++) {
            float ra[TM], rb[TN];
#pragma unroll
            for (int v = 0; v < TM / 4; v++)
                *(float4*)&ra[v * 4] = *(float4*)&As[buf][kk * GPA + ty * TM + v * 4];
#pragma unroll
            for (int v = 0; v < TN / 4; v++)
                *(float4*)&rb[v * 4] = *(float4*)&Bs[buf][kk * GPB + tx * TN + v * 4];
#pragma unroll
            for (int i = 0; i < TM; i++)
#pragma unroll
                for (int j = 0; j < TN; j++)
                    acc[i][j] += ra[i] * rb[j];
        }
        if (kt + 1 < nk) {
            buf ^= 1;
            stA(buf); stB(buf);
            __syncthreads();
        }
    }

#pragma unroll
    for (int i = 0; i < TM; i++) {
        int m = m0 + ty * TM + i;
        if (m >= M) continue;
#pragma unroll
        for (int j = 0; j < TN; j += 4) {
            int n = n0 + tx * TN + j;
            if (n >= N) continue;
            float4 v;
            v.x = alpha * acc[i][j + 0] + (bias ? bias[n + 0] : 0.f);
            v.y = alpha * acc[i][j + 1] + (bias ? bias[n + 1] : 0.f);
            v.z = alpha * acc[i][j + 2] + (bias ? bias[n + 2] : 0.f);
            v.w = alpha * acc[i][j + 3] + (bias ? bias[n + 3] : 0.f);
            *(float4*)(C + (long)m * ldc + n) = v;
        }
    }
}

// ---------------------------------------------------------------------------
// Softmax over contiguous groups of 64 (= r within each head). One warp/group.
// ---------------------------------------------------------------------------
__global__ __launch_bounds__(256)
void softmax_kernel(float* __restrict__ S, int ngroups)
{
    const int lane = threadIdx.x & 31;
    int wid = blockIdx.x * (blockDim.x >> 5) + (threadIdx.x >> 5);
    const int nw = gridDim.x * (blockDim.x >> 5);
    for (int g = wid; g < ngroups; g += nw) {
        float* p = S + (long)g * 64;
        float v0 = p[lane], v1 = p[lane + 32];
        float m = fmaxf(v0, v1);
#pragma unroll
        for (int off = 16; off > 0; off >>= 1)
            m = fmaxf(m, __shfl_xor_sync(0xFFFFFFFFu, m, off));
        float e0 = __expf(v0 - m), e1 = __expf(v1 - m);
        float s = e0 + e1;
#pragma unroll
        for (int off = 16; off > 0; off >>= 1)
            s += __shfl_xor_sync(0xFFFFFFFFu, s, off);
        float inv = 1.f / s;
        p[lane] = e0 * inv;
        p[lane + 32] = e1 * inv;
    }
}

// ---------------------------------------------------------------------------
extern "C" void kernel_launch(void* const* d_in, const int* in_sizes, int n_in,
                              void* d_out, int out_size)
{
    const float* x  = (const float*)d_in[0];
    const float* Wq = (const float*)d_in[1];
    const float* Wk = (const float*)d_in[2];
    const float* Wv = (const float*)d_in[3];
    const float* Wo = (const float*)d_in[4];
    const float* bo = (const float*)d_in[5];
    const float* E  = (const float*)d_in[6];
    const float* Fm = (const float*)d_in[7];
    float* out = (float*)d_out;

    float* base = nullptr;
    cudaGetSymbolAddress((void**)&base, g_scratch);
    float* xE = base + OFF_XE;
    float* xF = base + OFF_XF;
    float* KL = base + OFF_KL;
    float* VL = base + OFF_VL;
    float* Wt = base + OFF_WT;
    float* Mt = base + OFF_MT;
    float* S  = base + OFF_S;

    // 1. xE = E^T @ x[b], xF = Fm^T @ x[b]
    lowrank_kernel<<<dim3(16, 4, 2), 256>>>(x, E, Fm, xE, xF);

    // 2. KL = xE @ Wk^T, VL = xF @ Wv^T   (view xE as 256x1024, batch folded into rows)
    gemm_nt_kernel<64, 64, 4, 4, 16><<<dim3(16, 4, 1), 256>>>(
        xE, D_, Wk, D_, KL, D_, B_ * R_, D_, D_,
        1.f, nullptr, 1, 0, 0, 0, 0, 0, 0, 0);
    gemm_nt_kernel<64, 64, 4, 4, 16><<<dim3(16, 4, 1), 256>>>(
        xF, D_, Wv, D_, VL, D_, B_ * R_, D_, D_,
        1.f, nullptr, 1, 0, 0, 0, 0, 0, 0, 0);

    // 3a. Wt[b][h*64+r][d] = (1/8) * sum_hd KL[b][r][h*64+hd] * Wq[h*64+hd][d]
    //     z = b*16+h ; B operand is [K][N] (NN)
    gemm_nt_kernel<64, 64, 4, 4, 16><<<dim3(16, 1, B_ * H_), 256>>>(
        KL, D_, Wq, D_, Wt, D_, 64, D_, 64,
        0.125f, nullptr, H_,
        (long)R_ * D_, 64,          // A: b-stride, h-stride (col offset h*64)
        0, (long)64 * D_,           // B: Wq row block h*64
        (long)D_ * D_, (long)64 * D_,  // C: b-stride, row block h*64
        1);

    // 3b. Mt[b][e][h*64+r] = sum_hd Wo[e][h*64+hd] * VL[b][r][h*64+hd]   (NT)
    gemm_nt_kernel<64, 64, 4, 4, 16><<<dim3(1, 16, B_ * H_), 256>>>(
        Wo, D_, VL, D_, Mt, D_, D_, 64, 64,
        1.f, nullptr, H_,
        0, 64,                      // A: Wo col block h*64
        (long)R_ * D_, 64,          // B: VL b-stride, col block h*64
        (long)D_ * D_, 64,          // C: b-stride, col block h*64
        0);

    // 4. S[b] = x[b] @ Wt[b]^T   (scores, 1/scale already folded into Wt)
    gemm_nt_kernel<128, 128, 8, 8, 8><<<dim3(8, 32, B_), 256>>>(
        x, D_, Wt, D_, S, D_, N_, D_, D_,
        1.f, nullptr, 1,
        (long)N_ * D_, 0, (long)D_ * D_, 0, (long)N_ * D_, 0, 0);

    // 5. softmax over each 64-wide r-group (in place)
    softmax_kernel<<<2048, 256>>>(S, B_ * N_ * H_);

    // 6. out[b] = S[b] @ Mt[b]^T + bo
    gemm_nt_kernel<128, 128, 8, 8, 8><<<dim3(8, 32, B_), 256>>>(
        S, D_, Mt, D_, out, D_, N_, D_, D_,
        1.f, bo, 1,
        (long)N_ * D_, 0, (long)D_ * D_, 0, (long)N_ * D_, 0, 0);
}

// round 10
// speedup vs baseline: 2.3110x; 2.3110x over previous
#include <cuda_runtime.h>
#include <cuda_bf16.h>
#include <cstdint>

// LinformerAttention: B=4, N=4096, D=1024, H=16, R=64, HD=64
// Restructured (exact reassociation of reference):
//   xE[b,r,d]  = sum_n E[n,r]  * x[b,n,d]        (SIMT)
//   xF[b,r,d]  = sum_n Fm[n,r] * x[b,n,d]        (SIMT)
//   KL = xE@Wk^T, VL = xF@Wv^T                   (SIMT, small)
//   Wt[b,h*64+r,d] = (1/8) KL[b,r,h*64+:]·Wq[h*64+:,d]   (SIMT, small)
//   Mt[b,e,h*64+r] = VL[b,r,h*64+:]·Wo[e,h*64+:]         (SIMT, small)
//   S   = x @ Wt^T   per batch        (mma.sync bf16x3 — tcgen05 is an 'a'-feature
//                                      unavailable at this toolchain's compute_103)
//   softmax per 64-group on S
//   out = S @ Mt^T + bo  per batch    (mma.sync bf16x3)

#define B_ 4
#define N_ 4096
#define D_ 1024
#define H_ 16
#define R_ 64
#define MTOT (B_*N_)   // 16384

#define OFF_XE 0
#define OFF_XF (OFF_XE + B_*R_*D_)
#define OFF_KL (OFF_XF + B_*R_*D_)
#define OFF_VL (OFF_KL + B_*R_*D_)
#define OFF_WT (OFF_VL + B_*R_*D_)
#define OFF_MT (OFF_WT + B_*D_*D_)
#define OFF_S  (OFF_MT + B_*D_*D_)
#define SCRATCH_TOTAL (OFF_S + (long)B_*N_*D_)

__device__ float g_scratch[SCRATCH_TOTAL];
__device__ __nv_bfloat16 g_xhi[(long)MTOT*D_];
__device__ __nv_bfloat16 g_xlo[(long)MTOT*D_];
__device__ __nv_bfloat16 g_Whi[(long)B_*D_*D_];
__device__ __nv_bfloat16 g_Wlo[(long)B_*D_*D_];
__device__ __nv_bfloat16 g_Mhi[(long)B_*D_*D_];
__device__ __nv_bfloat16 g_Mlo[(long)B_*D_*D_];
__device__ __nv_bfloat16 g_Shi[(long)MTOT*D_];
__device__ __nv_bfloat16 g_Slo[(long)MTOT*D_];

// ======================= baseline-ISA helpers (no 'a'-features) ==========
__device__ __forceinline__ uint32_t smem_u32(const void* p) {
    uint32_t a;
    asm("{ .reg .u64 t; cvta.to.shared.u64 t, %1; cvt.u32.u64 %0, t; }" : "=r"(a) : "l"(p));
    return a;
}
__device__ __forceinline__ void cp_async16(uint32_t dst, const void* src) {
    asm volatile("cp.async.cg.shared.global [%0], [%1], 16;" :: "r"(dst), "l"(src));
}
#define CP_COMMIT() asm volatile("cp.async.commit_group;" ::: "memory")
#define CP_WAIT1()  asm volatile("cp.async.wait_group 1;" ::: "memory")
#define CP_WAIT0()  asm volatile("cp.async.wait_group 0;" ::: "memory")

__device__ __forceinline__ void ldmx4(uint32_t* r, uint32_t addr) {
    asm volatile("ldmatrix.sync.aligned.m8n8.x4.shared.b16 {%0,%1,%2,%3}, [%4];"
                 : "=r"(r[0]), "=r"(r[1]), "=r"(r[2]), "=r"(r[3]) : "r"(addr));
}
__device__ __forceinline__ void mma16816(float* d, const uint32_t* a, const uint32_t* b) {
    asm volatile(
        "mma.sync.aligned.m16n8k16.row.col.f32.bf16.bf16.f32 "
        "{%0,%1,%2,%3}, {%4,%5,%6,%7}, {%8,%9}, {%0,%1,%2,%3};"
        : "+f"(d[0]), "+f"(d[1]), "+f"(d[2]), "+f"(d[3])
        : "r"(a[0]), "r"(a[1]), "r"(a[2]), "r"(a[3]), "r"(b[0]), "r"(b[1]));
}

// ======================= big GEMM on tensor cores (mma.sync) ============
// C[m][n](+bias) = sum over 3 passes p of Ap[m][k]*Bp[bat][n][k], fp32 accum.
// Passes: (Ahi,Bhi), (Ahi,Blo), (Alo,Bhi)  — bf16x3 fp32 emulation.
// CTA tile 128x128, BK=32 (virtual K = 3*1024 = 96 chunks), 256 thr / 8 warps.
// Warp tile 32x64: 2 (m16) x 8 (n8) mma frags.
// SMEM per stage: A 128x64B, B 128x64B; 16B-chunk XOR swizzle (row>>1)&3 —
// conflict-free for both cp.async stores and ldmatrix reads.

#define BKC 32    // k per chunk (bf16)
#define NKV 96    // 3 passes * (1024/32)

__global__ __launch_bounds__(256)
void mma_gemm_kernel(const __nv_bfloat16* __restrict__ Ahi,
                     const __nv_bfloat16* __restrict__ Alo,
                     const __nv_bfloat16* __restrict__ Bhi,
                     const __nv_bfloat16* __restrict__ Blo,
                     float* __restrict__ C,
                     const float* __restrict__ bias)
{
    __shared__ __align__(16) char smem[4 * 8192];   // A s0,s1 ; B s0,s1
    const uint32_t sbase = smem_u32(smem);
    const uint32_t smA = sbase;           // +8192*s
    const uint32_t smB = sbase + 16384;   // +8192*s

    const int tid  = threadIdx.x;
    const int lane = tid & 31;
    const int wid  = tid >> 5;
    const int wm   = wid & 3;    // 4 warps along M, 32 rows each
    const int wn   = wid >> 2;   // 2 warps along N, 64 cols each

    const int n0 = blockIdx.x * 128;
    const int m0 = blockIdx.y * 128;
    const long bOff = (long)(m0 >> 12) * D_ * D_;   // batch = m0/4096

    float acc[2][8][4];
#pragma unroll
    for (int i = 0; i < 2; i++)
#pragma unroll
        for (int j = 0; j < 8; j++)
#pragma unroll
            for (int q = 0; q < 4; q++) acc[i][j][q] = 0.f;

    // ---- async loader: one BK chunk (A 8KB + B 8KB) into stage s ----
    auto load_stage = [&](int s, int kt) {
        const int p  = kt >> 5;            // pass 0,1,2
        const int k0 = (kt & 31) * BKC;
        const __nv_bfloat16* Ag = (p < 2) ? Ahi : Alo;
        const __nv_bfloat16* Bg = ((p == 1) ? Blo : Bhi) + bOff;
        const uint32_t sA = smA + s * 8192;
        const uint32_t sB = smB + s * 8192;
#pragma unroll
        for (int i = 0; i < 2; i++) {
            int idx = tid + i * 256;            // 0..511
            int row = idx >> 2, c = idx & 3;    // 128 rows x 4 chunks of 16B
            uint32_t so = (uint32_t)(row * 64 + ((c ^ ((row >> 1) & 3)) << 4));
            cp_async16(sA + so, Ag + (long)(m0 + row) * D_ + k0 + c * 8);
            cp_async16(sB + so, Bg + (long)(n0 + row) * D_ + k0 + c * 8);
        }
        CP_COMMIT();
    };

    // ---- compute one staged BK chunk ----
    auto compute_stage = [&](int s) {
        const uint32_t sA = smA + s * 8192;
        const uint32_t sB = smB + s * 8192;
#pragma unroll
        for (int ks = 0; ks < 2; ks++) {       // two k16 halves
            uint32_t a[2][4];
#pragma unroll
            for (int mt = 0; mt < 2; mt++) {
                int row = wm * 32 + mt * 16 + ((lane >> 3) & 1) * 8 + (lane & 7);
                int ch  = 2 * ks + (lane >> 4);
                ldmx4(a[mt], sA + row * 64 + ((ch ^ ((row >> 1) & 3)) << 4));
            }
            uint32_t b[8][2];
#pragma unroll
            for (int nb = 0; nb < 4; nb++) {
                int row = wn * 64 + nb * 16 + ((lane >> 3) & 1) * 8 + (lane & 7);
                int ch  = 2 * ks + (lane >> 4);
                uint32_t r[4];
                ldmx4(r, sB + row * 64 + ((ch ^ ((row >> 1) & 3)) << 4));
                b[2 * nb][0] = r[0]; b[2 * nb + 1][0] = r[1];
                b[2 * nb][1] = r[2]; b[2 * nb + 1][1] = r[3];
            }
#pragma unroll
            for (int mt = 0; mt < 2; mt++)
#pragma unroll
                for (int nt = 0; nt < 8; nt++)
                    mma16816(acc[mt][nt], a[mt], b[nt]);
        }
    };

    load_stage(0, 0);
    for (int kt = 0; kt < NKV; kt++) {
        if (kt + 1 < NKV) { load_stage((kt + 1) & 1, kt + 1); CP_WAIT1(); }
        else              { CP_WAIT0(); }
        __syncthreads();
        compute_stage(kt & 1);
        __syncthreads();
    }

    // ---- epilogue: fragment c0..c3 -> C rows (m, m+8), cols n..n+1 ----
#pragma unroll
    for (int mt = 0; mt < 2; mt++) {
        int m = m0 + wm * 32 + mt * 16 + (lane >> 2);
#pragma unroll
        for (int nt = 0; nt < 8; nt++) {
            int n = n0 + wn * 64 + nt * 8 + (lane & 3) * 2;
            float bx = 0.f, by = 0.f;
            if (bias) { bx = bias[n]; by = bias[n + 1]; }
            float2 v0 = make_float2(acc[mt][nt][0] + bx, acc[mt][nt][1] + by);
            float2 v1 = make_float2(acc[mt][nt][2] + bx, acc[mt][nt][3] + by);
            *(float2*)(C + (long)m * D_ + n) = v0;
            *(float2*)(C + (long)(m + 8) * D_ + n) = v1;
        }
    }
}

// ======================= split fp32 -> bf16 hi/lo =======================
__global__ __launch_bounds__(256)
void split_kernel(const float* __restrict__ in, __nv_bfloat16* __restrict__ hi,
                  __nv_bfloat16* __restrict__ lo, int n4)
{
    int i = blockIdx.x * blockDim.x + threadIdx.x;
    if (i >= n4) return;
    float4 v = *(const float4*)(in + (long)i * 4);
    __nv_bfloat16 h0 = __float2bfloat16(v.x), h1 = __float2bfloat16(v.y);
    __nv_bfloat16 h2 = __float2bfloat16(v.z), h3 = __float2bfloat16(v.w);
    __nv_bfloat16 l0 = __float2bfloat16(v.x - __bfloat162float(h0));
    __nv_bfloat16 l1 = __float2bfloat16(v.y - __bfloat162float(h1));
    __nv_bfloat16 l2 = __float2bfloat16(v.z - __bfloat162float(h2));
    __nv_bfloat16 l3 = __float2bfloat16(v.w - __bfloat162float(h3));
    ((__nv_bfloat162*)hi)[(long)i * 2 + 0] = __nv_bfloat162(h0, h1);
    ((__nv_bfloat162*)hi)[(long)i * 2 + 1] = __nv_bfloat162(h2, h3);
    ((__nv_bfloat162*)lo)[(long)i * 2 + 0] = __nv_bfloat162(l0, l1);
    ((__nv_bfloat162*)lo)[(long)i * 2 + 1] = __nv_bfloat162(l2, l3);
}

// ======================= lowrank reduce =======================
__global__ __launch_bounds__(256)
void lowrank_kernel(const float* __restrict__ x, const float* __restrict__ E,
                    const float* __restrict__ Fm, float* __restrict__ xE,
                    float* __restrict__ xF)
{
    __shared__ float Ps[32][64];
    __shared__ float Xs[32][64];
    const float* P = blockIdx.z ? Fm : E;
    float* OUT = blockIdx.z ? xF : xE;
    const int b = blockIdx.y;
    const int d0 = blockIdx.x * 64;
    const int t = threadIdx.x;
    const int tx = t & 15, ty = t >> 4;
    const float* xb = x + (long)b * N_ * D_;

    float acc[4][4];
#pragma unroll
    for (int i = 0; i < 4; i++)
#pragma unroll
        for (int j = 0; j < 4; j++) acc[i][j] = 0.f;

    for (int n0 = 0; n0 < N_; n0 += 32) {
#pragma unroll
        for (int l = t; l < 512; l += 256) {
            int row = l >> 4, q = (l & 15) * 4;
            *(float4*)&Ps[row][q] = *(const float4*)&P[(long)(n0 + row) * R_ + q];
            *(float4*)&Xs[row][q] = *(const float4*)&xb[(long)(n0 + row) * D_ + d0 + q];
        }
        __syncthreads();
#pragma unroll
        for (int n = 0; n < 32; n++) {
            float4 a = *(float4*)&Ps[n][ty * 4];
            float4 c = *(float4*)&Xs[n][tx * 4];
            float ra[4] = {a.x, a.y, a.z, a.w};
            float rc[4] = {c.x, c.y, c.z, c.w};
#pragma unroll
            for (int i = 0; i < 4; i++)
#pragma unroll
                for (int j = 0; j < 4; j++) acc[i][j] += ra[i] * rc[j];
        }
        __syncthreads();
    }
#pragma unroll
    for (int i = 0; i < 4; i++) {
        float4 v = make_float4(acc[i][0], acc[i][1], acc[i][2], acc[i][3]);
        *(float4*)&OUT[((long)b * R_ + ty * 4 + i) * D_ + d0 + tx * 4] = v;
    }
}

// ======================= small SIMT GEMM =======================
template<int BM, int BN, int TM, int TN, int BK>
__global__ __launch_bounds__(256)
void gemm_nt_kernel(const float* __restrict__ Ag, int lda,
                    const float* __restrict__ Bg, int ldb,
                    float* __restrict__ Cg, int ldc,
                    int M, int N, int K,
                    float alpha, const float* __restrict__ bias,
                    int zdiv,
                    long sA1, long sA2, long sB1, long sB2, long sC1, long sC2,
                    int b_is_kn)
{
    static_assert(BM * BK == 1024 && BN * BK == 1024, "load mapping");
    static_assert((BN / TN) * (BM / TM) == 256, "thread grid");
    constexpr int GPA = BM + 4;
    constexpr int GPB = BN + 4;
    __shared__ float As[2][BK * GPA];
    __shared__ float Bs[2][BK * GPB];

    const int z = blockIdx.z;
    const long z1 = z / zdiv, z2 = z % zdiv;
    const float* A = Ag + z1 * sA1 + z2 * sA2;
    const float* Bp = Bg + z1 * sB1 + z2 * sB2;
    float* C = Cg + z1 * sC1 + z2 * sC2;

    const int m0 = blockIdx.y * BM;
    const int n0 = blockIdx.x * BN;
    const int t  = threadIdx.x;
    const int tx = t % (BN / TN);
    const int ty = t / (BN / TN);

    constexpr int KQ = BK / 4;
    const int arow = t / KQ;
    const int akq  = (t % KQ) * 4;
    const int bkrow = t / (BN / 4);
    const int bnq   = (t % (BN / 4)) * 4;

    const bool amask = (m0 + arow) < M;
    const bool bmask_nt = (n0 + arow) < N;
    const bool bmask_nn = (n0 + bnq) < N;

    float acc[TM][TN];
#pragma unroll
    for (int i = 0; i < TM; i++)
#pragma unroll
        for (int j = 0; j < TN; j++) acc[i][j] = 0.f;

    float4 pa, pb;
    const float4 z4 = make_float4(0.f, 0.f, 0.f, 0.f);

    auto ldA = [&](int k0) {
        pa = amask ? *(const float4*)(A + (long)(m0 + arow) * lda + k0 + akq) : z4;
    };
    auto ldB = [&](int k0) {
        if (b_is_kn)
            pb = bmask_nn ? *(const float4*)(Bp + (long)(k0 + bkrow) * ldb + n0 + bnq) : z4;
        else
            pb = bmask_nt ? *(const float4*)(Bp + (long)(n0 + arow) * ldb + k0 + akq) : z4;
    };
    auto stA = [&](int buf) {
        As[buf][(akq + 0) * GPA + arow] = pa.x;
        As[buf][(akq + 1) * GPA + arow] = pa.y;
        As[buf][(akq + 2) * GPA + arow] = pa.z;
        As[buf][(akq + 3) * GPA + arow] = pa.w;
    };
    auto stB = [&](int buf) {
        if (b_is_kn) {
            *(float4*)&Bs[buf][bkrow * GPB + bnq] = pb;
        } else {
            Bs[buf][(akq + 0) * GPB + arow] = pb.x;
            Bs[buf][(akq + 1) * GPB + arow] = pb.y;
            Bs[buf][(akq + 2) * GPB + arow] = pb.z;
            Bs[buf][(akq + 3) * GPB + arow] = pb.w;
        }
    };

    ldA(0); ldB(0);
    stA(0); stB(0);
    __syncthreads();

    const int nk = K / BK;
    int buf = 0;
    for (int kt = 0; kt < nk; kt++) {
        if (kt + 1 < nk) { ldA((kt + 1) * BK); ldB((kt + 1) * BK); }
#pragma unroll
        for (int kk = 0; kk < BK; kk++) {
            float ra[TM], rb[TN];
#pragma unroll
            for (int v = 0; v < TM / 4; v++)
                *(float4*)&ra[v * 4] = *(float4*)&As[buf][kk * GPA + ty * TM + v * 4];
#pragma unroll
            for (int v = 0; v < TN / 4; v++)
                *(float4*)&rb[v * 4] = *(float4*)&Bs[buf][kk * GPB + tx * TN + v * 4];
#pragma unroll
            for (int i = 0; i < TM; i++)
#pragma unroll
                for (int j = 0; j < TN; j++)
                    acc[i][j] += ra[i] * rb[j];
        }
        if (kt + 1 < nk) {
            buf ^= 1;
            stA(buf); stB(buf);
            __syncthreads();
        }
    }

#pragma unroll
    for (int i = 0; i < TM; i++) {
        int m = m0 + ty * TM + i;
        if (m >= M) continue;
#pragma unroll
        for (int j = 0; j < TN; j += 4) {
            int n = n0 + tx * TN + j;
            if (n >= N) continue;
            float4 v;
            v.x = alpha * acc[i][j + 0] + (bias ? bias[n + 0] : 0.f);
            v.y = alpha * acc[i][j + 1] + (bias ? bias[n + 1] : 0.f);
            v.z = alpha * acc[i][j + 2] + (bias ? bias[n + 2] : 0.f);
            v.w = alpha * acc[i][j + 3] + (bias ? bias[n + 3] : 0.f);
            *(float4*)(C + (long)m * ldc + n) = v;
        }
    }
}

// ======================= softmax + bf16 split output =======================
__global__ __launch_bounds__(256)
void softmax_split_kernel(const float* __restrict__ S,
                          __nv_bfloat16* __restrict__ Shi,
                          __nv_bfloat16* __restrict__ Slo, int ngroups)
{
    const int lane = threadIdx.x & 31;
    int wid = blockIdx.x * (blockDim.x >> 5) + (threadIdx.x >> 5);
    const int nw = gridDim.x * (blockDim.x >> 5);
    for (int g = wid; g < ngroups; g += nw) {
        const float* p = S + (long)g * 64;
        float v0 = p[lane], v1 = p[lane + 32];
        float m = fmaxf(v0, v1);
#pragma unroll
        for (int off = 16; off > 0; off >>= 1)
            m = fmaxf(m, __shfl_xor_sync(0xFFFFFFFFu, m, off));
        float e0 = __expf(v0 - m), e1 = __expf(v1 - m);
        float s = e0 + e1;
#pragma unroll
        for (int off = 16; off > 0; off >>= 1)
            s += __shfl_xor_sync(0xFFFFFFFFu, s, off);
        float inv = 1.f / s;
        float a0 = e0 * inv, a1 = e1 * inv;
        __nv_bfloat16 h0 = __float2bfloat16(a0);
        __nv_bfloat16 h1 = __float2bfloat16(a1);
        Shi[(long)g * 64 + lane] = h0;
        Shi[(long)g * 64 + lane + 32] = h1;
        Slo[(long)g * 64 + lane] = __float2bfloat16(a0 - __bfloat162float(h0));
        Slo[(long)g * 64 + lane + 32] = __float2bfloat16(a1 - __bfloat162float(h1));
    }
}

// ===========================================================================
extern "C" void kernel_launch(void* const* d_in, const int* in_sizes, int n_in,
                              void* d_out, int out_size)
{
    const float* x  = (const float*)d_in[0];
    const float* Wq = (const float*)d_in[1];
    const float* Wk = (const float*)d_in[2];
    const float* Wv = (const float*)d_in[3];
    const float* Wo = (const float*)d_in[4];
    const float* bo = (const float*)d_in[5];
    const float* E  = (const float*)d_in[6];
    const float* Fm = (const float*)d_in[7];
    float* out = (float*)d_out;

    float* base = nullptr;
    cudaGetSymbolAddress((void**)&base, g_scratch);
    float* xE = base + OFF_XE;
    float* xF = base + OFF_XF;
    float* KL = base + OFF_KL;
    float* VL = base + OFF_VL;
    float* Wt = base + OFF_WT;
    float* Mt = base + OFF_MT;
    float* S  = base + OFF_S;

    __nv_bfloat16 *xhi, *xlo, *Whi, *Wlo, *Mhi, *Mlo, *Shi, *Slo;
    cudaGetSymbolAddress((void**)&xhi, g_xhi);
    cudaGetSymbolAddress((void**)&xlo, g_xlo);
    cudaGetSymbolAddress((void**)&Whi, g_Whi);
    cudaGetSymbolAddress((void**)&Wlo, g_Wlo);
    cudaGetSymbolAddress((void**)&Mhi, g_Mhi);
    cudaGetSymbolAddress((void**)&Mlo, g_Mlo);
    cudaGetSymbolAddress((void**)&Shi, g_Shi);
    cudaGetSymbolAddress((void**)&Slo, g_Slo);

    // 1. low-rank sequence reductions
    lowrank_kernel<<<dim3(16, 4, 2), 256>>>(x, E, Fm, xE, xF);

    // split x -> bf16 hi/lo (independent of step 1)
    split_kernel<<<(MTOT * D_ / 4 + 255) / 256, 256>>>(x, xhi, xlo, MTOT * D_ / 4);

    // 2. KL = xE @ Wk^T, VL = xF @ Wv^T
    gemm_nt_kernel<64, 64, 4, 4, 16><<<dim3(16, 4, 1), 256>>>(
        xE, D_, Wk, D_, KL, D_, B_ * R_, D_, D_,
        1.f, nullptr, 1, 0, 0, 0, 0, 0, 0, 0);
    gemm_nt_kernel<64, 64, 4, 4, 16><<<dim3(16, 4, 1), 256>>>(
        xF, D_, Wv, D_, VL, D_, B_ * R_, D_, D_,
        1.f, nullptr, 1, 0, 0, 0, 0, 0, 0, 0);

    // 3a. Wt (1/scale folded)
    gemm_nt_kernel<64, 64, 4, 4, 16><<<dim3(16, 1, B_ * H_), 256>>>(
        KL, D_, Wq, D_, Wt, D_, 64, D_, 64,
        0.125f, nullptr, H_,
        (long)R_ * D_, 64, 0, (long)64 * D_,
        (long)D_ * D_, (long)64 * D_, 1);

    // 3b. Mt
    gemm_nt_kernel<64, 64, 4, 4, 16><<<dim3(1, 16, B_ * H_), 256>>>(
        Wo, D_, VL, D_, Mt, D_, D_, 64, 64,
        1.f, nullptr, H_,
        0, 64, (long)R_ * D_, 64,
        (long)D_ * D_, 64, 0);

    // split Wt, Mt
    split_kernel<<<(B_ * D_ * D_ / 4 + 255) / 256, 256>>>(Wt, Whi, Wlo, B_ * D_ * D_ / 4);
    split_kernel<<<(B_ * D_ * D_ / 4 + 255) / 256, 256>>>(Mt, Mhi, Mlo, B_ * D_ * D_ / 4);

    // 4. S = x @ Wt^T (tensor cores, bf16x3)
    mma_gemm_kernel<<<dim3(D_ / 128, MTOT / 128), 256>>>(
        xhi, xlo, Whi, Wlo, S, nullptr);

    // 5. softmax per 64-group, emit bf16 hi/lo
    softmax_split_kernel<<<2048, 256>>>(S, Shi, Slo, B_ * N_ * H_);

    // 6. out = S @ Mt^T + bo (tensor cores, bf16x3)
    mma_gemm_kernel<<<dim3(D_ / 128, MTOT / 128), 256>>>(
        Shi, Slo, Mhi, Mlo, out, bo);
}